// round 2
// baseline (speedup 1.0000x reference)
#include <cuda_runtime.h>

// Problem constants (shapes fixed by the dataset)
#define NB   16          // batch
#define C    256         // channels
#define HH   128
#define WW   128
#define HW   (HH*WW)     // 16384 pixels per image
#define CLS  9
#define P    (NB*HW)     // 262144 total pixels
#define NT   256         // threads per block
#define NBLK_ARG ((P/4)/NT)   // 256 argmax blocks
#define NPLANE (NB*C)         // 4096 (n,c) planes

// Scratch (no allocations allowed; every word fully overwritten each replay)
__device__ unsigned char g_labels[P];
__device__ int           g_cnt_part[NBLK_ARG * CLS];   // per-argmax-block counts
__device__ float         g_part[NPLANE * CLS];         // per-(n,c) class sums

// ---------------------------------------------------------------------------
// 1) per-pixel argmax over CLS logit planes -> labels[P] (uint8)
//    + per-block class counts (plain stores, no atomics on global)
// ---------------------------------------------------------------------------
__global__ void __launch_bounds__(NT) argmax_kernel(const float* __restrict__ logit) {
    __shared__ int s_cnt[CLS];
    const int tid = threadIdx.x;
    if (tid < CLS) s_cnt[tid] = 0;
    __syncthreads();

    const int g   = blockIdx.x * NT + tid;   // float4-group index
    const int n   = g >> 12;                 // g / (HW/4)
    const int hw4 = g & 4095;                // g % (HW/4)

    const float4* lp = (const float4*)logit;
    float4 best = lp[(size_t)(n*CLS + 0) * (HW/4) + hw4];
    uchar4 lab  = make_uchar4(0,0,0,0);
    #pragma unroll
    for (int cls = 1; cls < CLS; cls++) {
        float4 v = lp[(size_t)(n*CLS + cls) * (HW/4) + hw4];
        if (v.x > best.x) { best.x = v.x; lab.x = (unsigned char)cls; }
        if (v.y > best.y) { best.y = v.y; lab.y = (unsigned char)cls; }
        if (v.z > best.z) { best.z = v.z; lab.z = (unsigned char)cls; }
        if (v.w > best.w) { best.w = v.w; lab.w = (unsigned char)cls; }
    }
    ((uchar4*)g_labels)[g] = lab;

    atomicAdd(&s_cnt[lab.x], 1);
    atomicAdd(&s_cnt[lab.y], 1);
    atomicAdd(&s_cnt[lab.z], 1);
    atomicAdd(&s_cnt[lab.w], 1);
    __syncthreads();
    if (tid < CLS) g_cnt_part[blockIdx.x * CLS + tid] = s_cnt[tid];
}

// ---------------------------------------------------------------------------
// 2) accumulate: one block per (n,c) plane. Streams the plane (float4) with
//    the matching labels (uchar4, L2-resident) into per-thread SMEM columns
//    acc[cls][tid] (bank-conflict-free). Tail: warp shfl butterfly + 8-way
//    cross-warp sum, then 9 plain stores to g_part (no atomics).
// ---------------------------------------------------------------------------
__global__ void __launch_bounds__(NT) accum_kernel(const float* __restrict__ feat) {
    __shared__ float acc[CLS * NT];
    __shared__ float s_warp[CLS * 8];       // per-warp partials
    const int tid = threadIdx.x;
    #pragma unroll
    for (int l = 0; l < CLS; l++) acc[l*NT + tid] = 0.0f;
    __syncthreads();

    const int nc = blockIdx.x;        // 0..NPLANE-1
    const int n  = nc >> 8;           // nc / C

    const float4* fp = (const float4*)feat + (size_t)nc * (HW/4);
    const uchar4* lp = (const uchar4*)g_labels + (size_t)n * (HW/4);

    #pragma unroll
    for (int k = 0; k < (HW/4)/NT; k++) {   // 16 iterations
        const int i = tid + k*NT;
        float4 v = fp[i];
        uchar4 l = lp[i];
        acc[l.x*NT + tid] += v.x;
        acc[l.y*NT + tid] += v.y;
        acc[l.z*NT + tid] += v.z;
        acc[l.w*NT + tid] += v.w;
    }
    __syncthreads();

    // warp-level butterfly reduce for all 9 classes
    float v[CLS];
    #pragma unroll
    for (int l = 0; l < CLS; l++) v[l] = acc[l*NT + tid];
    #pragma unroll
    for (int off = 16; off > 0; off >>= 1) {
        #pragma unroll
        for (int l = 0; l < CLS; l++)
            v[l] += __shfl_xor_sync(0xFFFFFFFFu, v[l], off);
    }
    const int warp = tid >> 5, lane = tid & 31;
    if (lane == 0) {
        #pragma unroll
        for (int l = 0; l < CLS; l++) s_warp[l*8 + warp] = v[l];
    }
    __syncthreads();

    if (tid < CLS) {
        float s = 0.0f;
        #pragma unroll
        for (int w = 0; w < 8; w++) s += s_warp[tid*8 + w];
        g_part[nc*CLS + tid] = s;   // plain store, private slot
    }
}

// ---------------------------------------------------------------------------
// 3) finalize: ONE block. Reduce per-block counts (256x9) and per-plane
//    partials (4096x9, L2-resident), then broadcast means to out [NB,C,CLS].
// ---------------------------------------------------------------------------
__global__ void __launch_bounds__(NT) out_kernel(float* __restrict__ out) {
    __shared__ float s_wcnt[CLS * 8];
    __shared__ float s_inv[CLS];
    const int tid = threadIdx.x;

    // counts: thread t owns argmax block t (exactly 256 blocks)
    float c[CLS];
    #pragma unroll
    for (int l = 0; l < CLS; l++) c[l] = (float)g_cnt_part[tid*CLS + l];
    #pragma unroll
    for (int off = 16; off > 0; off >>= 1) {
        #pragma unroll
        for (int l = 0; l < CLS; l++)
            c[l] += __shfl_xor_sync(0xFFFFFFFFu, c[l], off);
    }
    const int warp = tid >> 5, lane = tid & 31;
    if (lane == 0) {
        #pragma unroll
        for (int l = 0; l < CLS; l++) s_wcnt[l*8 + warp] = c[l];
    }
    __syncthreads();
    if (tid < CLS) {
        float s = 0.0f;
        #pragma unroll
        for (int w = 0; w < 8; w++) s += s_wcnt[tid*8 + w];
        s_inv[tid] = 1.0f / fmaxf(s, 1.0f);
    }
    __syncthreads();

    // sums + broadcast: 2304 (c,cls) pairs, 9 per thread, 16 partials each
    #pragma unroll
    for (int r = 0; r < (C*CLS)/NT; r++) {      // 9 rounds
        const int idx = r*NT + tid;             // 0..2303
        const int ch  = idx / CLS;
        const int cls = idx - ch*CLS;
        float s = 0.0f;
        #pragma unroll
        for (int n = 0; n < NB; n++)
            s += g_part[(n*C + ch)*CLS + cls];
        const float val = s * s_inv[cls];
        #pragma unroll
        for (int n = 0; n < NB; n++)
            out[n*(C*CLS) + idx] = val;
    }
}

// ---------------------------------------------------------------------------
extern "C" void kernel_launch(void* const* d_in, const int* in_sizes, int n_in,
                              void* d_out, int out_size) {
    const float* feat  = (const float*)d_in[0];
    const float* logit = (const float*)d_in[1];
    float* out = (float*)d_out;

    argmax_kernel<<<NBLK_ARG, NT>>>(logit);   // 256 blocks
    accum_kernel<<<NPLANE, NT>>>(feat);       // 4096 blocks
    out_kernel<<<1, NT>>>(out);               // 1 block
}

// round 3
// speedup vs baseline: 1.0104x; 1.0104x over previous
#include <cuda_runtime.h>

// Problem constants (shapes fixed by the dataset)
#define NB   16
#define C    256
#define HW   16384          // 128*128
#define CLS  9
#define P    (NB*HW)        // 262144 pixels
#define NT   256
#define NBLK_ARG (P/NT)     // 1024 argmax blocks (1 pixel/thread)
#define NCHUNK (NB*C*2)     // 8192 half-plane chunks
#define ITERS  8            // float4 groups per thread per chunk: 2048/256

// Scratch (no allocation; every word fully overwritten each replay)
__device__ unsigned char g_labels[P];
__device__ int           g_cnt_part[NBLK_ARG * CLS];
__device__ float         g_part[NCHUNK * CLS];

// ---------------------------------------------------------------------------
// 1) per-pixel argmax -> labels[P] + per-block class counts
// ---------------------------------------------------------------------------
__global__ void __launch_bounds__(NT) argmax_kernel(const float* __restrict__ logit) {
    __shared__ int s_cnt[CLS];
    const int tid = threadIdx.x;
    if (tid < CLS) s_cnt[tid] = 0;
    __syncthreads();

    const int p  = blockIdx.x * NT + tid;
    const int n  = p >> 14;              // p / HW
    const int hw = p & 16383;

    const float* lp = logit + (size_t)n * CLS * HW + hw;
    float best = lp[0];
    int   lab  = 0;
    #pragma unroll
    for (int cls = 1; cls < CLS; cls++) {
        float v = lp[(size_t)cls * HW];
        if (v > best) { best = v; lab = cls; }
    }
    g_labels[p] = (unsigned char)lab;

    atomicAdd(&s_cnt[lab], 1);
    __syncthreads();
    if (tid < CLS) g_cnt_part[blockIdx.x * CLS + tid] = s_cnt[tid];
}

// ---------------------------------------------------------------------------
// 2) accumulate: one block per half-plane chunk (8192 blocks, 8 iters).
//    Front-batch ALL 16 global loads into registers (MLP_p1=16), then do
//    bank-conflict-free smem scatter acc[cls][tid]. Tail: shfl butterfly.
// ---------------------------------------------------------------------------
__global__ void __launch_bounds__(NT) accum_kernel(const float* __restrict__ feat) {
    __shared__ float acc[CLS * NT];
    __shared__ float s_warp[CLS * 8];
    const int tid = threadIdx.x;
    #pragma unroll
    for (int l = 0; l < CLS; l++) acc[l*NT + tid] = 0.0f;
    __syncthreads();

    const int chunk = blockIdx.x;        // 0..NCHUNK-1
    const int nc    = chunk >> 1;
    const int half  = chunk & 1;
    const int n     = nc >> 8;

    const float4* fp = (const float4*)feat     + (size_t)nc * 4096 + half * 2048;
    const uchar4* lp = (const uchar4*)g_labels + (size_t)n  * 4096 + half * 2048;

    // front-batched loads: 8 float4 + 8 uchar4, all independent
    float4 v[ITERS];
    uchar4 l[ITERS];
    #pragma unroll
    for (int k = 0; k < ITERS; k++) v[k] = fp[tid + k*NT];
    #pragma unroll
    for (int k = 0; k < ITERS; k++) l[k] = lp[tid + k*NT];

    #pragma unroll
    for (int k = 0; k < ITERS; k++) {
        acc[l[k].x*NT + tid] += v[k].x;
        acc[l[k].y*NT + tid] += v[k].y;
        acc[l[k].z*NT + tid] += v[k].z;
        acc[l[k].w*NT + tid] += v[k].w;
    }
    __syncthreads();

    // butterfly reduce over the warp for all 9 classes
    float s[CLS];
    #pragma unroll
    for (int c = 0; c < CLS; c++) s[c] = acc[c*NT + tid];
    #pragma unroll
    for (int off = 16; off > 0; off >>= 1) {
        #pragma unroll
        for (int c = 0; c < CLS; c++)
            s[c] += __shfl_xor_sync(0xFFFFFFFFu, s[c], off);
    }
    const int warp = tid >> 5, lane = tid & 31;
    if (lane == 0) {
        #pragma unroll
        for (int c = 0; c < CLS; c++) s_warp[c*8 + warp] = s[c];
    }
    __syncthreads();

    if (tid < CLS) {
        float t = 0.0f;
        #pragma unroll
        for (int w = 0; w < 8; w++) t += s_warp[tid*8 + w];
        g_part[chunk*CLS + tid] = t;     // plain store, private slot
    }
}

// ---------------------------------------------------------------------------
// 3) finalize: 9 blocks x 256 threads. Each thread owns one (ch,cls) pair:
//    sum 32 L2-resident partials, scale by 1/count, broadcast over batch.
//    Counts (1024x9) reduced redundantly in every block (cheap, L2-hot).
// ---------------------------------------------------------------------------
__global__ void __launch_bounds__(NT) out_kernel(float* __restrict__ out) {
    __shared__ float s_wcnt[CLS * 8];
    __shared__ float s_inv[CLS];
    const int tid = threadIdx.x;

    // counts: thread t sums argmax blocks t, t+256, t+512, t+768
    float c[CLS];
    #pragma unroll
    for (int l = 0; l < CLS; l++) c[l] = 0.0f;
    #pragma unroll
    for (int r = 0; r < NBLK_ARG/NT; r++) {
        #pragma unroll
        for (int l = 0; l < CLS; l++)
            c[l] += (float)g_cnt_part[(r*NT + tid)*CLS + l];
    }
    #pragma unroll
    for (int off = 16; off > 0; off >>= 1) {
        #pragma unroll
        for (int l = 0; l < CLS; l++)
            c[l] += __shfl_xor_sync(0xFFFFFFFFu, c[l], off);
    }
    const int warp = tid >> 5, lane = tid & 31;
    if (lane == 0) {
        #pragma unroll
        for (int l = 0; l < CLS; l++) s_wcnt[l*8 + warp] = c[l];
    }
    __syncthreads();
    if (tid < CLS) {
        float s = 0.0f;
        #pragma unroll
        for (int w = 0; w < 8; w++) s += s_wcnt[tid*8 + w];
        s_inv[tid] = 1.0f / fmaxf(s, 1.0f);
    }
    __syncthreads();

    const int idx = blockIdx.x * NT + tid;   // 0..2303 (C*CLS)
    if (idx >= C*CLS) return;
    const int ch  = idx / CLS;
    const int cls = idx - ch*CLS;

    float s = 0.0f;
    #pragma unroll
    for (int n = 0; n < NB; n++) {
        const int base = ((n*C + ch) * 2) * CLS + cls;
        s += g_part[base] + g_part[base + CLS];
    }
    const float val = s * s_inv[cls];
    #pragma unroll
    for (int n = 0; n < NB; n++)
        out[n*(C*CLS) + idx] = val;
}

// ---------------------------------------------------------------------------
extern "C" void kernel_launch(void* const* d_in, const int* in_sizes, int n_in,
                              void* d_out, int out_size) {
    const float* feat  = (const float*)d_in[0];
    const float* logit = (const float*)d_in[1];
    float* out = (float*)d_out;

    argmax_kernel<<<NBLK_ARG, NT>>>(logit);          // 1024 blocks
    accum_kernel<<<NCHUNK, NT>>>(feat);              // 8192 blocks
    out_kernel<<<(C*CLS + NT - 1)/NT, NT>>>(out);    // 9 blocks
}

// round 4
// speedup vs baseline: 1.0816x; 1.0704x over previous
#include <cuda_runtime.h>

// Problem constants (shapes fixed by the dataset)
#define NB   16
#define C    256
#define HW   16384          // 128*128
#define CLS  9
#define P    (NB*HW)        // 262144 pixels
#define NT   256
#define NBLK_ARG ((P/2)/NT) // 512 argmax blocks (2 pixels/thread, float2)
#define NPLANE (NB*C)       // 4096 (n,c) planes

// Scratch (no allocation; every word fully overwritten each replay)
__device__ unsigned char g_labels[P];
__device__ int           g_cnt_part[NBLK_ARG * CLS];
__device__ float         g_part[NPLANE * CLS];

// ---------------------------------------------------------------------------
// 1) per-pixel argmax (float2, 2 pixels/thread) -> labels + per-block counts
// ---------------------------------------------------------------------------
__global__ void __launch_bounds__(NT) argmax_kernel(const float* __restrict__ logit) {
    __shared__ int s_cnt[CLS];
    const int tid = threadIdx.x;
    if (tid < CLS) s_cnt[tid] = 0;
    __syncthreads();

    const int g   = blockIdx.x * NT + tid;   // float2-group index, 0..P/2-1
    const int n   = g >> 13;                 // g / (HW/2)
    const int hw2 = g & 8191;

    const float2* lp = (const float2*)logit;
    float2 best = lp[(size_t)(n*CLS + 0) * (HW/2) + hw2];
    int lx = 0, ly = 0;
    #pragma unroll
    for (int cls = 1; cls < CLS; cls++) {
        float2 v = lp[(size_t)(n*CLS + cls) * (HW/2) + hw2];
        if (v.x > best.x) { best.x = v.x; lx = cls; }
        if (v.y > best.y) { best.y = v.y; ly = cls; }
    }
    ((unsigned char*)g_labels)[2*g]   = (unsigned char)lx;
    ((unsigned char*)g_labels)[2*g+1] = (unsigned char)ly;

    atomicAdd(&s_cnt[lx], 1);
    atomicAdd(&s_cnt[ly], 1);
    __syncthreads();
    if (tid < CLS) g_cnt_part[blockIdx.x * CLS + tid] = s_cnt[tid];
}

// ---------------------------------------------------------------------------
// 2) accumulate: one block per (n,c) plane (4096 blocks, 16 iters).
//    Plain loop -> low registers -> 8 resident blocks/SM (R1 structure).
//    Bank-conflict-free smem scatter acc[cls][tid], shfl-butterfly tail,
//    plain private stores (no atomics).
// ---------------------------------------------------------------------------
__global__ void __launch_bounds__(NT) accum_kernel(const float* __restrict__ feat) {
    __shared__ float acc[CLS * NT];
    __shared__ float s_warp[CLS * 8];
    const int tid = threadIdx.x;
    #pragma unroll
    for (int l = 0; l < CLS; l++) acc[l*NT + tid] = 0.0f;
    __syncthreads();

    const int nc = blockIdx.x;        // 0..NPLANE-1
    const int n  = nc >> 8;           // nc / C

    const float4* fp = (const float4*)feat     + (size_t)nc * (HW/4);
    const uchar4* lp = (const uchar4*)g_labels + (size_t)n  * (HW/4);

    #pragma unroll
    for (int k = 0; k < (HW/4)/NT; k++) {   // 16 iterations
        const int i = tid + k*NT;
        float4 v = fp[i];
        uchar4 l = lp[i];
        acc[l.x*NT + tid] += v.x;
        acc[l.y*NT + tid] += v.y;
        acc[l.z*NT + tid] += v.z;
        acc[l.w*NT + tid] += v.w;
    }
    __syncthreads();

    // butterfly reduce over the warp for all 9 classes
    float s[CLS];
    #pragma unroll
    for (int c = 0; c < CLS; c++) s[c] = acc[c*NT + tid];
    #pragma unroll
    for (int off = 16; off > 0; off >>= 1) {
        #pragma unroll
        for (int c = 0; c < CLS; c++)
            s[c] += __shfl_xor_sync(0xFFFFFFFFu, s[c], off);
    }
    const int warp = tid >> 5, lane = tid & 31;
    if (lane == 0) {
        #pragma unroll
        for (int c = 0; c < CLS; c++) s_warp[c*8 + warp] = s[c];
    }
    __syncthreads();

    if (tid < CLS) {
        float t = 0.0f;
        #pragma unroll
        for (int w = 0; w < 8; w++) t += s_warp[tid*8 + w];
        g_part[nc*CLS + tid] = t;     // plain store, private slot
    }
}

// ---------------------------------------------------------------------------
// 3) finalize: 9 blocks x 256 threads. Each thread owns one (ch,cls) pair:
//    sum 16 L2-resident partials, scale by 1/count, broadcast over batch.
//    Counts (512x9) reduced redundantly per block (cheap, L2-hot).
// ---------------------------------------------------------------------------
__global__ void __launch_bounds__(NT) out_kernel(float* __restrict__ out) {
    __shared__ float s_wcnt[CLS * 8];
    __shared__ float s_inv[CLS];
    const int tid = threadIdx.x;

    // counts: thread t sums argmax blocks t and t+256
    float c[CLS];
    #pragma unroll
    for (int l = 0; l < CLS; l++)
        c[l] = (float)g_cnt_part[tid*CLS + l]
             + (float)g_cnt_part[(tid + NT)*CLS + l];
    #pragma unroll
    for (int off = 16; off > 0; off >>= 1) {
        #pragma unroll
        for (int l = 0; l < CLS; l++)
            c[l] += __shfl_xor_sync(0xFFFFFFFFu, c[l], off);
    }
    const int warp = tid >> 5, lane = tid & 31;
    if (lane == 0) {
        #pragma unroll
        for (int l = 0; l < CLS; l++) s_wcnt[l*8 + warp] = c[l];
    }
    __syncthreads();
    if (tid < CLS) {
        float s = 0.0f;
        #pragma unroll
        for (int w = 0; w < 8; w++) s += s_wcnt[tid*8 + w];
        s_inv[tid] = 1.0f / fmaxf(s, 1.0f);
    }
    __syncthreads();

    const int idx = blockIdx.x * NT + tid;   // 0..2303 (C*CLS)
    if (idx >= C*CLS) return;
    const int ch  = idx / CLS;
    const int cls = idx - ch*CLS;

    float s = 0.0f;
    #pragma unroll
    for (int n = 0; n < NB; n++)
        s += g_part[(n*C + ch)*CLS + cls];
    const float val = s * s_inv[cls];
    #pragma unroll
    for (int n = 0; n < NB; n++)
        out[n*(C*CLS) + idx] = val;
}

// ---------------------------------------------------------------------------
extern "C" void kernel_launch(void* const* d_in, const int* in_sizes, int n_in,
                              void* d_out, int out_size) {
    const float* feat  = (const float*)d_in[0];
    const float* logit = (const float*)d_in[1];
    float* out = (float*)d_out;

    argmax_kernel<<<NBLK_ARG, NT>>>(logit);          // 512 blocks
    accum_kernel<<<NPLANE, NT>>>(feat);              // 4096 blocks
    out_kernel<<<(C*CLS + NT - 1)/NT, NT>>>(out);    // 9 blocks
}